// round 16
// baseline (speedup 1.0000x reference)
#include <cuda_runtime.h>
#include <cuda_bf16.h>
#include <cstdint>

#define B_TOTAL        65536
#define N_K            64
#define ROW_FLOATS     (N_K * 3)          // 192 floats per row per tensor
#define DEGREE         3
#define SAMPLES        20
#define ROWS_PER_BLOCK 16
#define THREADS        160                 // each thread: sample j of rows r and r+8
#define NBLOCKS        (B_TOTAL / ROWS_PER_BLOCK)  // 4096
#define KF_LEN         68                 // 4 zeros + 64 knots (fp32, exact search)
#define C_LEN          68                 // 64 bf16x2 coeff words + 4 pad

__device__ double        g_sum;     // zero-init; reset by last block each run
__device__ unsigned int  g_count;   // zero-init; reset by last block each run

// Packed f32x2 helpers (sm_103a native paired fp32 pipes).
__device__ __forceinline__ uint64_t pack2(float lo, float hi) {
    uint64_t r;
    asm("mov.b64 %0, {%1, %2};" : "=l"(r) : "f"(lo), "f"(hi));
    return r;
}
__device__ __forceinline__ void unpack2(uint64_t v, float& lo, float& hi) {
    asm("mov.b64 {%0, %1}, %2;" : "=f"(lo), "=f"(hi) : "l"(v));
}
__device__ __forceinline__ uint64_t sub_f32x2(uint64_t a, uint64_t b) {
    uint64_t r;
    asm("sub.rn.f32x2 %0, %1, %2;" : "=l"(r) : "l"(a), "l"(b));
    return r;
}
__device__ __forceinline__ uint64_t fma_f32x2(uint64_t a, uint64_t b, uint64_t c) {
    uint64_t r;
    asm("fma.rn.f32x2 %0, %1, %2, %3;" : "=l"(r) : "l"(a), "l"(b), "l"(c));
    return r;
}

// De Boor sample. kf padded fp32; coeffs packed bf16x2 (x=lo, y=hi).
// denom provably > 0 (strictly increasing knots, spacing >= 0.1): no guard.
__device__ __forceinline__ uint64_t deboor_eval(const float*    __restrict__ kf,
                                                const unsigned* __restrict__ c,
                                                float t, int i0)
{
    float kfv[7];
#pragma unroll
    for (int m = 1; m < 7; m++) kfv[m] = kf[i0 + m];   // kfv[0] never used

    uint64_t p[4];                     // packed (x, y) control points
#pragma unroll
    for (int k = 0; k < 4; k++) {
        unsigned w = c[i0 + k];
        float2 v = __bfloat1622float2(*reinterpret_cast<__nv_bfloat162*>(&w));
        p[k] = pack2(v.x, v.y);
    }

#pragma unroll
    for (int l = 1; l <= DEGREE; l++) {
#pragma unroll
        for (int k = 3; k >= 1; k--) {
            if (k < l) break;
            float ki = kfv[k];
            float alpha = __fdividef(t - ki, kfv[k + 4 - l] - ki);
            uint64_t a2 = pack2(alpha, alpha);
            p[k] = fma_f32x2(a2, sub_f32x2(p[k], p[k - 1]), p[k - 1]);
        }
    }
    return p[3];   // homogeneous weight stays exactly 1 -> no division
}

// Coarse search: steps 32,16,8,4 (no bound guard needed: max probe index 60,
// i.e. kf[63], in bounds). Leaves a = i0 & ~3.
__device__ __forceinline__ void quad_coarse(const float* __restrict__ k0, float t0,
                                            const float* __restrict__ k1, float t1,
                                            const float* __restrict__ k2, float t2,
                                            const float* __restrict__ k3, float t3,
                                            int& a0, int& a1, int& a2, int& a3)
{
    a0 = a1 = a2 = a3 = 0;
#pragma unroll
    for (int step = 32; step >= 4; step >>= 1) {
        int c0 = a0 + step, c1 = a1 + step, c2 = a2 + step, c3 = a3 + step;
        if (k0[c0 + 3] <= t0) a0 = c0;
        if (k1[c1 + 3] <= t1) a1 = c1;
        if (k2[c2 + 3] <= t2) a2 = c2;
        if (k3[c3 + 3] <= t3) a3 = c3;
    }
}

// Fine step: one aligned LDS.128 (a%4==0 -> kf+a+4 is 16B aligned) replaces
// the step=2 and step=1 probes. Guard a<60 covers the i0<=60 bound.
__device__ __forceinline__ int fine3(const float* __restrict__ kf, int a, float t)
{
    float4 k4 = *reinterpret_cast<const float4*>(kf + a + 4);  // knots a..a+3
    int cnt = 0;
    if (a < 60) cnt = (int)(k4.x <= t) + (int)(k4.y <= t) + (int)(k4.z <= t);
    return a + cnt;
}

__global__ __launch_bounds__(THREADS)
void bspline_loss_fused(const float* __restrict__ pred,
                        const float* __restrict__ tru,
                        float* __restrict__ out)
{
    __shared__ __align__(16) float    s_kf[2][ROWS_PER_BLOCK][KF_LEN];
    __shared__ __align__(16) unsigned s_c [2][ROWS_PER_BLOCK][C_LEN];

    // Zero kf padding with STS.128: 32 (tensor,row) pairs.
    if (threadIdx.x < 2 * ROWS_PER_BLOCK) {
        int tsel = threadIdx.x >> 4;
        int r    = threadIdx.x & 15;
        *reinterpret_cast<float4*>(&s_kf[tsel][r][0]) = make_float4(0.f, 0.f, 0.f, 0.f);
    }

    // Hoist `high` (= knots[60], float offset 180 in row) from global into
    // registers BEFORE the transpose: broadcast loads, overlapped with the
    // tile loads, so t needs no LDS after the barrier.
    const int rA = threadIdx.x / SAMPLES;          // 0..7
    const int rB = rA + 8;                         // 8..15
    const int j  = threadIdx.x % SAMPLES;
    const size_t base = (size_t)blockIdx.x * ROWS_PER_BLOCK * ROW_FLOATS;
    const float hAp = __ldg(pred + base + (size_t)rA * ROW_FLOATS + 180);
    const float hAt = __ldg(tru  + base + (size_t)rA * ROW_FLOATS + 180);
    const float hBp = __ldg(pred + base + (size_t)rB * ROW_FLOATS + 180);
    const float hBt = __ldg(tru  + base + (size_t)rB * ROW_FLOATS + 180);

    // Wide transpose: 1 item = 4 triples = 3 LDG.128 in, 1 fp32 STS.128 (knots)
    // + 1 packed-bf16x2 STS.128 (4 coeff points) out.
    // items = 2 tensors x 16 rows x 16 groups = 512.
    {
        const float4* gp = reinterpret_cast<const float4*>(pred + base);
        const float4* gt = reinterpret_cast<const float4*>(tru + base);
        const int G = 2 * ROWS_PER_BLOCK * 16;
        for (int g = threadIdx.x; g < G; g += THREADS) {
            const int tsel = g >> 8;           // 0..1
            const int r    = (g >> 4) & 15;    // 0..15
            const int grp  = g & 15;           // 0..15 -> elements 4*grp..4*grp+3
            const float4* src = tsel ? gt : gp;
            const int idx4 = 48 * r + 3 * grp;
            float4 v0 = src[idx4 + 0];   // k0 x0 y0 k1
            float4 v1 = src[idx4 + 1];   // x1 y1 k2 x2
            float4 v2 = src[idx4 + 2];   // y2 k3 x3 y3
            const int i = 4 * grp;
            *reinterpret_cast<float4*>(&s_kf[tsel][r][4 + i]) =
                make_float4(v0.x, v0.w, v1.z, v2.y);

            __nv_bfloat162 c0 = __float22bfloat162_rn(make_float2(v0.y, v0.z));
            __nv_bfloat162 c1 = __float22bfloat162_rn(make_float2(v1.x, v1.y));
            __nv_bfloat162 c2 = __float22bfloat162_rn(make_float2(v1.w, v2.x));
            __nv_bfloat162 c3 = __float22bfloat162_rn(make_float2(v2.z, v2.w));
            uint4 packed;
            packed.x = *reinterpret_cast<unsigned*>(&c0);
            packed.y = *reinterpret_cast<unsigned*>(&c1);
            packed.z = *reinterpret_cast<unsigned*>(&c2);
            packed.w = *reinterpret_cast<unsigned*>(&c3);
            *reinterpret_cast<uint4*>(&s_c[tsel][r][i]) = packed;
        }
    }
    __syncthreads();

    // 4 independent work chains: rows rA, rB for pred and true.
    const float frac = (float)j / 19.0f;
    const float tAp = frac * hAp;
    const float tAt = frac * hAt;
    const float tBp = frac * hBp;
    const float tBt = frac * hBt;

    const float* kAp = &s_kf[0][rA][0];
    const float* kAt = &s_kf[1][rA][0];
    const float* kBp = &s_kf[0][rB][0];
    const float* kBt = &s_kf[1][rB][0];

    int aAp, aAt, aBp, aBt;
    quad_coarse(kAp, tAp, kAt, tAt, kBp, tBp, kBt, tBt, aAp, aAt, aBp, aBt);
    const int iAp = fine3(kAp, aAp, tAp);
    const int iAt = fine3(kAt, aAt, tAt);
    const int iBp = fine3(kBp, aBp, tBp);
    const int iBt = fine3(kBt, aBt, tBt);

    uint64_t sAp = deboor_eval(kAp, &s_c[0][rA][0], tAp, iAp);
    uint64_t sAt = deboor_eval(kAt, &s_c[1][rA][0], tAt, iAt);
    uint64_t sBp = deboor_eval(kBp, &s_c[0][rB][0], tBp, iBp);
    uint64_t sBt = deboor_eval(kBt, &s_c[1][rB][0], tBt, iBt);

    uint64_t dA = sub_f32x2(sAp, sAt);
    uint64_t dB = sub_f32x2(sBp, sBt);
    float dxA, dyA, dxB, dyB;
    unpack2(dA, dxA, dyA);
    unpack2(dB, dxB, dyB);
    float val = fmaf(dxA, dxA, dyA * dyA) + fmaf(dxB, dxB, dyB * dyB);

    // Warp reduce (5 full warps).
#pragma unroll
    for (int o = 16; o > 0; o >>= 1)
        val += __shfl_down_sync(0xFFFFFFFFu, val, o);

    __shared__ float warpsum[THREADS / 32];
    const int wid  = threadIdx.x >> 5;
    const int lane = threadIdx.x & 31;
    if (lane == 0) warpsum[wid] = val;
    __syncthreads();

    if (threadIdx.x == 0) {
        double tot = 0.0;
#pragma unroll
        for (int w = 0; w < THREADS / 32; w++) tot += (double)warpsum[w];
        atomicAdd(&g_sum, tot);
        __threadfence();
        unsigned int ticket = atomicAdd(&g_count, 1u);
        if (ticket == NBLOCKS - 1) {
            out[0] = (float)(g_sum / (double)((long long)B_TOTAL * SAMPLES));
            g_sum = 0.0;
            __threadfence();
            g_count = 0u;
        }
    }
}

extern "C" void kernel_launch(void* const* d_in, const int* in_sizes, int n_in,
                              void* d_out, int out_size)
{
    const float* pred = (const float*)d_in[0];
    const float* tru  = (const float*)d_in[1];
    float* out = (float*)d_out;

    bspline_loss_fused<<<NBLOCKS, THREADS>>>(pred, tru, out);
}

// round 17
// speedup vs baseline: 1.4298x; 1.4298x over previous
#include <cuda_runtime.h>
#include <cuda_bf16.h>
#include <cstdint>

#define B_TOTAL        65536
#define N_K            64
#define ROW_FLOATS     (N_K * 3)          // 192 floats per row per tensor
#define DEGREE         3
#define SAMPLES        20
#define ROWS_PER_BLOCK 16
#define THREADS        160                 // each thread: sample j of rows r and r+8
#define NBLOCKS        (B_TOTAL / ROWS_PER_BLOCK)  // 4096
#define KF_LEN         68                 // 4 zeros + 64 knots (fp32, exact search)
#define C_LEN          68                 // 64 bf16x2 coeff words + 4 pad

__device__ double        g_sum;     // zero-init; reset by last block each run
__device__ unsigned int  g_count;   // zero-init; reset by last block each run

// Packed f32x2 helpers (sm_103a native paired fp32 pipes).
__device__ __forceinline__ uint64_t pack2(float lo, float hi) {
    uint64_t r;
    asm("mov.b64 %0, {%1, %2};" : "=l"(r) : "f"(lo), "f"(hi));
    return r;
}
__device__ __forceinline__ void unpack2(uint64_t v, float& lo, float& hi) {
    asm("mov.b64 {%0, %1}, %2;" : "=f"(lo), "=f"(hi) : "l"(v));
}
__device__ __forceinline__ uint64_t sub_f32x2(uint64_t a, uint64_t b) {
    uint64_t r;
    asm("sub.rn.f32x2 %0, %1, %2;" : "=l"(r) : "l"(a), "l"(b));
    return r;
}
__device__ __forceinline__ uint64_t fma_f32x2(uint64_t a, uint64_t b, uint64_t c) {
    uint64_t r;
    asm("fma.rn.f32x2 %0, %1, %2, %3;" : "=l"(r) : "l"(a), "l"(b), "l"(c));
    return r;
}

// De Boor sample. kf padded fp32; coeffs packed bf16x2 (x=lo, y=hi).
// denom provably > 0 (strictly increasing knots, spacing >= 0.1): no guard.
__device__ __forceinline__ uint64_t deboor_eval(const float*    __restrict__ kf,
                                                const unsigned* __restrict__ c,
                                                float t, int i0)
{
    float kfv[7];
#pragma unroll
    for (int m = 1; m < 7; m++) kfv[m] = kf[i0 + m];   // kfv[0] never used

    uint64_t p[4];                     // packed (x, y) control points
#pragma unroll
    for (int k = 0; k < 4; k++) {
        unsigned w = c[i0 + k];
        float2 v = __bfloat1622float2(*reinterpret_cast<__nv_bfloat162*>(&w));
        p[k] = pack2(v.x, v.y);
    }

#pragma unroll
    for (int l = 1; l <= DEGREE; l++) {
#pragma unroll
        for (int k = 3; k >= 1; k--) {
            if (k < l) break;
            float ki = kfv[k];
            float alpha = __fdividef(t - ki, kfv[k + 4 - l] - ki);
            uint64_t a2 = pack2(alpha, alpha);
            p[k] = fma_f32x2(a2, sub_f32x2(p[k], p[k - 1]), p[k - 1]);
        }
    }
    return p[3];   // homogeneous weight stays exactly 1 -> no division
}

// Coarse search: steps 32,16,8,4 (no bound guard needed: max probe index 60,
// i.e. kf[63], in bounds). Leaves a = i0 & ~3.
__device__ __forceinline__ void quad_coarse(const float* __restrict__ k0, float t0,
                                            const float* __restrict__ k1, float t1,
                                            const float* __restrict__ k2, float t2,
                                            const float* __restrict__ k3, float t3,
                                            int& a0, int& a1, int& a2, int& a3)
{
    a0 = a1 = a2 = a3 = 0;
#pragma unroll
    for (int step = 32; step >= 4; step >>= 1) {
        int c0 = a0 + step, c1 = a1 + step, c2 = a2 + step, c3 = a3 + step;
        if (k0[c0 + 3] <= t0) a0 = c0;
        if (k1[c1 + 3] <= t1) a1 = c1;
        if (k2[c2 + 3] <= t2) a2 = c2;
        if (k3[c3 + 3] <= t3) a3 = c3;
    }
}

// Fine step: one aligned LDS.128 (a%4==0 -> kf+a+4 is 16B aligned) replaces
// the step=2 and step=1 probes. Guard a<60 covers the i0<=60 bound.
__device__ __forceinline__ int fine3(const float* __restrict__ kf, int a, float t)
{
    float4 k4 = *reinterpret_cast<const float4*>(kf + a + 4);  // knots a..a+3
    int cnt = 0;
    if (a < 60) cnt = (int)(k4.x <= t) + (int)(k4.y <= t) + (int)(k4.z <= t);
    return a + cnt;
}

__global__ __launch_bounds__(THREADS, 12)   // pin regs <= 34 -> 12 blocks/SM
void bspline_loss_fused(const float* __restrict__ pred,
                        const float* __restrict__ tru,
                        float* __restrict__ out)
{
    __shared__ __align__(16) float    s_kf[2][ROWS_PER_BLOCK][KF_LEN];
    __shared__ __align__(16) unsigned s_c [2][ROWS_PER_BLOCK][C_LEN];

    // Zero kf padding with STS.128: 32 (tensor,row) pairs.
    if (threadIdx.x < 2 * ROWS_PER_BLOCK) {
        int tsel = threadIdx.x >> 4;
        int r    = threadIdx.x & 15;
        *reinterpret_cast<float4*>(&s_kf[tsel][r][0]) = make_float4(0.f, 0.f, 0.f, 0.f);
    }

    // Hoist `high` (= knots[60], float offset 180 in row) from global into
    // registers BEFORE the transpose: broadcast loads, overlapped with the
    // tile loads, so t needs no LDS after the barrier.
    const int rA = threadIdx.x / SAMPLES;          // 0..7
    const int rB = rA + 8;                         // 8..15
    const int j  = threadIdx.x % SAMPLES;
    const size_t base = (size_t)blockIdx.x * ROWS_PER_BLOCK * ROW_FLOATS;
    const float hAp = __ldg(pred + base + (size_t)rA * ROW_FLOATS + 180);
    const float hAt = __ldg(tru  + base + (size_t)rA * ROW_FLOATS + 180);
    const float hBp = __ldg(pred + base + (size_t)rB * ROW_FLOATS + 180);
    const float hBt = __ldg(tru  + base + (size_t)rB * ROW_FLOATS + 180);

    // Wide transpose: 1 item = 4 triples = 3 LDG.128 in, 1 fp32 STS.128 (knots)
    // + 1 packed-bf16x2 STS.128 (4 coeff points) out.
    // items = 2 tensors x 16 rows x 16 groups = 512.
    {
        const float4* gp = reinterpret_cast<const float4*>(pred + base);
        const float4* gt = reinterpret_cast<const float4*>(tru + base);
        const int G = 2 * ROWS_PER_BLOCK * 16;
        for (int g = threadIdx.x; g < G; g += THREADS) {
            const int tsel = g >> 8;           // 0..1
            const int r    = (g >> 4) & 15;    // 0..15
            const int grp  = g & 15;           // 0..15 -> elements 4*grp..4*grp+3
            const float4* src = tsel ? gt : gp;
            const int idx4 = 48 * r + 3 * grp;
            float4 v0 = src[idx4 + 0];   // k0 x0 y0 k1
            float4 v1 = src[idx4 + 1];   // x1 y1 k2 x2
            float4 v2 = src[idx4 + 2];   // y2 k3 x3 y3
            const int i = 4 * grp;
            *reinterpret_cast<float4*>(&s_kf[tsel][r][4 + i]) =
                make_float4(v0.x, v0.w, v1.z, v2.y);

            __nv_bfloat162 c0 = __float22bfloat162_rn(make_float2(v0.y, v0.z));
            __nv_bfloat162 c1 = __float22bfloat162_rn(make_float2(v1.x, v1.y));
            __nv_bfloat162 c2 = __float22bfloat162_rn(make_float2(v1.w, v2.x));
            __nv_bfloat162 c3 = __float22bfloat162_rn(make_float2(v2.z, v2.w));
            uint4 packed;
            packed.x = *reinterpret_cast<unsigned*>(&c0);
            packed.y = *reinterpret_cast<unsigned*>(&c1);
            packed.z = *reinterpret_cast<unsigned*>(&c2);
            packed.w = *reinterpret_cast<unsigned*>(&c3);
            *reinterpret_cast<uint4*>(&s_c[tsel][r][i]) = packed;
        }
    }
    __syncthreads();

    // 4 independent work chains: rows rA, rB for pred and true.
    const float frac = (float)j / 19.0f;
    const float tAp = frac * hAp;
    const float tAt = frac * hAt;
    const float tBp = frac * hBp;
    const float tBt = frac * hBt;

    const float* kAp = &s_kf[0][rA][0];
    const float* kAt = &s_kf[1][rA][0];
    const float* kBp = &s_kf[0][rB][0];
    const float* kBt = &s_kf[1][rB][0];

    int aAp, aAt, aBp, aBt;
    quad_coarse(kAp, tAp, kAt, tAt, kBp, tBp, kBt, tBt, aAp, aAt, aBp, aBt);
    const int iAp = fine3(kAp, aAp, tAp);
    const int iAt = fine3(kAt, aAt, tAt);
    const int iBp = fine3(kBp, aBp, tBp);
    const int iBt = fine3(kBt, aBt, tBt);

    uint64_t sAp = deboor_eval(kAp, &s_c[0][rA][0], tAp, iAp);
    uint64_t sAt = deboor_eval(kAt, &s_c[1][rA][0], tAt, iAt);
    uint64_t sBp = deboor_eval(kBp, &s_c[0][rB][0], tBp, iBp);
    uint64_t sBt = deboor_eval(kBt, &s_c[1][rB][0], tBt, iBt);

    uint64_t dA = sub_f32x2(sAp, sAt);
    uint64_t dB = sub_f32x2(sBp, sBt);
    float dxA, dyA, dxB, dyB;
    unpack2(dA, dxA, dyA);
    unpack2(dB, dxB, dyB);
    float val = fmaf(dxA, dxA, dyA * dyA) + fmaf(dxB, dxB, dyB * dyB);

    // Warp reduce (5 full warps).
#pragma unroll
    for (int o = 16; o > 0; o >>= 1)
        val += __shfl_down_sync(0xFFFFFFFFu, val, o);

    __shared__ float warpsum[THREADS / 32];
    const int wid  = threadIdx.x >> 5;
    const int lane = threadIdx.x & 31;
    if (lane == 0) warpsum[wid] = val;
    __syncthreads();

    if (threadIdx.x == 0) {
        double tot = 0.0;
#pragma unroll
        for (int w = 0; w < THREADS / 32; w++) tot += (double)warpsum[w];
        atomicAdd(&g_sum, tot);
        __threadfence();
        unsigned int ticket = atomicAdd(&g_count, 1u);
        if (ticket == NBLOCKS - 1) {
            out[0] = (float)(g_sum / (double)((long long)B_TOTAL * SAMPLES));
            g_sum = 0.0;
            __threadfence();
            g_count = 0u;
        }
    }
}

extern "C" void kernel_launch(void* const* d_in, const int* in_sizes, int n_in,
                              void* d_out, int out_size)
{
    const float* pred = (const float*)d_in[0];
    const float* tru  = (const float*)d_in[1];
    float* out = (float*)d_out;

    bspline_loss_fused<<<NBLOCKS, THREADS>>>(pred, tru, out);
}